// round 1
// baseline (speedup 1.0000x reference)
#include <cuda_runtime.h>
#include <cstdint>
#include <math.h>

#define NG   256
#define NN   64
#define KNN  24
#define HID  128
#define NPAD 132   // padded row stride (floats) for 64x128 tiles
#define DPAD 66    // padded row stride (u64) for 64x64 key matrix

// Precomputed combined edge-conv weight: cols 0..127 = Wc_top - Wc_bot (for 'a'),
// cols 128..255 = Wc_bot (for 'p').  [128][256] row-major.
__device__ float g_Wcat[HID * 2 * HID];

__device__ __forceinline__ float elu1(float x) {
    return x > 0.f ? x : (__expf(x) - 1.f);
}

// monotonic uint encoding of float (total order matching < on floats)
__device__ __forceinline__ unsigned int fkey(float d) {
    unsigned int u = __float_as_uint(d);
    return ((int)u < 0) ? ~u : (u | 0x80000000u);
}

__global__ void prep_kernel(const float* __restrict__ Wc) {
    int i = blockIdx.x * blockDim.x + threadIdx.x;
    if (i < HID * 2 * HID) {
        int k = i >> 8;      // 0..127
        int c = i & 255;     // 0..255
        float v;
        if (c < HID) v = Wc[k * HID + c] - Wc[(HID + k) * HID + c];
        else         v = Wc[(HID + k) * HID + (c - HID)];
        g_Wcat[i] = v;
    }
}

// C[64 x 128] = act( Xin[64 x KD] @ W[KD x 128] + bias ), written to Out (stride NPAD)
__device__ __forceinline__ void gemm_nc128(const float* __restrict__ Xin, int xs, int KD,
                                           const float* __restrict__ W,
                                           const float* __restrict__ bias,
                                           float* __restrict__ Out, int t) {
    int n0 = (t >> 5) * 8;
    int c0 = (t & 31) * 4;
    float acc[8][4];
#pragma unroll
    for (int i = 0; i < 8; i++) { acc[i][0] = 0.f; acc[i][1] = 0.f; acc[i][2] = 0.f; acc[i][3] = 0.f; }
#pragma unroll 4
    for (int k = 0; k < KD; k++) {
        float4 w = *(const float4*)(W + k * 128 + c0);
#pragma unroll
        for (int i = 0; i < 8; i++) {
            float xv = Xin[(n0 + i) * xs + k];
            acc[i][0] = fmaf(xv, w.x, acc[i][0]);
            acc[i][1] = fmaf(xv, w.y, acc[i][1]);
            acc[i][2] = fmaf(xv, w.z, acc[i][2]);
            acc[i][3] = fmaf(xv, w.w, acc[i][3]);
        }
    }
    float4 b = *(const float4*)(bias + c0);
#pragma unroll
    for (int i = 0; i < 8; i++) {
        float4 r;
        r.x = elu1(acc[i][0] + b.x);
        r.y = elu1(acc[i][1] + b.y);
        r.z = elu1(acc[i][2] + b.z);
        r.w = elu1(acc[i][3] + b.w);
        *(float4*)(Out + (n0 + i) * NPAD + c0) = r;
    }
}

// [a|p] = Xin[64x128] @ g_Wcat[128x256]; a -> Aout, p -> Pout (both stride NPAD)
__device__ __forceinline__ void gemm_edge(const float* __restrict__ Xin,
                                          float* __restrict__ Aout,
                                          float* __restrict__ Pout, int t) {
    int n0 = (t >> 5) * 8;
    int c0 = (t & 31) * 8;
    float acc[8][8];
#pragma unroll
    for (int i = 0; i < 8; i++)
#pragma unroll
        for (int j = 0; j < 8; j++) acc[i][j] = 0.f;
#pragma unroll 2
    for (int k = 0; k < HID; k++) {
        const float* wr = g_Wcat + k * 256 + c0;
        float4 w0 = *(const float4*)(wr);
        float4 w1 = *(const float4*)(wr + 4);
#pragma unroll
        for (int i = 0; i < 8; i++) {
            float xv = Xin[(n0 + i) * NPAD + k];
            acc[i][0] = fmaf(xv, w0.x, acc[i][0]);
            acc[i][1] = fmaf(xv, w0.y, acc[i][1]);
            acc[i][2] = fmaf(xv, w0.z, acc[i][2]);
            acc[i][3] = fmaf(xv, w0.w, acc[i][3]);
            acc[i][4] = fmaf(xv, w1.x, acc[i][4]);
            acc[i][5] = fmaf(xv, w1.y, acc[i][5]);
            acc[i][6] = fmaf(xv, w1.z, acc[i][6]);
            acc[i][7] = fmaf(xv, w1.w, acc[i][7]);
        }
    }
    float* dst; int cc;
    if (c0 < 128) { dst = Aout; cc = c0; } else { dst = Pout; cc = c0 - 128; }
#pragma unroll
    for (int i = 0; i < 8; i++) {
        *(float4*)(dst + (n0 + i) * NPAD + cc)     = make_float4(acc[i][0], acc[i][1], acc[i][2], acc[i][3]);
        *(float4*)(dst + (n0 + i) * NPAD + cc + 4) = make_float4(acc[i][4], acc[i][5], acc[i][6], acc[i][7]);
    }
}

__global__ __launch_bounds__(256, 2)
void net_kernel(const float* __restrict__ x_pf,
                const float* __restrict__ W1, const float* __restrict__ b1,
                const float* __restrict__ W2, const float* __restrict__ b2,
                const float* __restrict__ bc,
                const float* __restrict__ Wo1, const float* __restrict__ bo1,
                const float* __restrict__ Wo2, const float* __restrict__ bo2,
                const float* __restrict__ Wo3, const float* __restrict__ bo3,
                const float* __restrict__ Wo4, const float* __restrict__ bo4,
                float* __restrict__ out, int write_batch) {
    extern __shared__ float sm[];
    float* Xs = sm;                   // 64*132 current node features
    float* As = Xs + NN * NPAD;       // 64*132 'a' term (aliases the u64 key matrix)
    float* Ps = As + NN * NPAD;       // 64*132 'p' term (also h1 scratch in stage 1)
    int*   idxs = (int*)(Ps + NN * NPAD);          // 64*24 KNN indices
    float* sq = (float*)(idxs + NN * KNN);         // 64 squared norms
    float* hd = sq + NN;                           // 256 floats head scratch
    unsigned long long* ds = (unsigned long long*)As;  // 64 x DPAD keys

    int g = blockIdx.x;
    int t = threadIdx.x;

    // ---------------- Stage 1: h = elu(elu(x@W1+b1)@W2+b2) ----------------
    float* Xi = As;  // temp [64][16]
    for (int i = t; i < NN * 15; i += 256) {
        int n = i / 15, f = i - n * 15;
        Xi[n * 16 + f] = x_pf[(g * NN + n) * 15 + f];
    }
    __syncthreads();
    gemm_nc128(Xi, 16, 15, W1, b1, Ps, t);
    __syncthreads();
    gemm_nc128(Ps, NPAD, 128, W2, b2, Xs, t);

    // ---------------- 3 x EdgeConv ----------------
    for (int layer = 0; layer < 3; layer++) {
        __syncthreads();  // Xs ready
        // squared norms
        if (t < NN) {
            float s = 0.f;
#pragma unroll 8
            for (int k4 = 0; k4 < 32; k4++) {
                float4 v = *(const float4*)(Xs + t * NPAD + k4 * 4);
                s += v.x * v.x + v.y * v.y + v.z * v.z + v.w * v.w;
            }
            sq[t] = s;
        }
        __syncthreads();
        // pairwise distance keys: d = sq_i + sq_j - 2 x_i.x_j
        {
            int r0 = (t >> 4) * 4, c0 = (t & 15) * 4;
            float acc[4][4];
#pragma unroll
            for (int i = 0; i < 4; i++)
#pragma unroll
                for (int j = 0; j < 4; j++) acc[i][j] = 0.f;
#pragma unroll 4
            for (int k4 = 0; k4 < 32; k4++) {
                float4 av[4], bv[4];
#pragma unroll
                for (int i = 0; i < 4; i++) av[i] = *(const float4*)(Xs + (r0 + i) * NPAD + k4 * 4);
#pragma unroll
                for (int j = 0; j < 4; j++) bv[j] = *(const float4*)(Xs + (c0 + j) * NPAD + k4 * 4);
#pragma unroll
                for (int i = 0; i < 4; i++)
#pragma unroll
                    for (int j = 0; j < 4; j++)
                        acc[i][j] += av[i].x * bv[j].x + av[i].y * bv[j].y +
                                     av[i].z * bv[j].z + av[i].w * bv[j].w;
            }
#pragma unroll
            for (int i = 0; i < 4; i++)
#pragma unroll
                for (int j = 0; j < 4; j++) {
                    float d = sq[r0 + i] + sq[c0 + j] - 2.f * acc[i][j];
                    ds[(r0 + i) * DPAD + (c0 + j)] =
                        ((unsigned long long)fkey(d) << 6) | (unsigned)(c0 + j);
                }
        }
        __syncthreads();
        // exact top-K by rank counting (strict total order => rank is the slot)
        {
            int i = t >> 2, jb = (t & 3) * 16;
            unsigned long long kj[16];
#pragma unroll
            for (int jj = 0; jj < 16; jj++) kj[jj] = ds[i * DPAD + jb + jj];
            int rk[16];
#pragma unroll
            for (int jj = 0; jj < 16; jj++) rk[jj] = 0;
            for (int m = 0; m < 64; m++) {
                unsigned long long km = ds[i * DPAD + m];
#pragma unroll
                for (int jj = 0; jj < 16; jj++) rk[jj] += (km < kj[jj]) ? 1 : 0;
            }
#pragma unroll
            for (int jj = 0; jj < 16; jj++)
                if (rk[jj] < KNN) idxs[i * KNN + rk[jj]] = jb + jj;
        }
        __syncthreads();  // keys dead; GEMM may overwrite As
        gemm_edge(Xs, As, Ps, t);
        __syncthreads();
        // gather-max over neighbors, then single elu (elu is monotonic)
        {
            int n = t >> 2, cb = t & 3;
            int id[KNN];
#pragma unroll
            for (int k = 0; k < KNN; k++) id[k] = idxs[n * KNN + k];
            for (int c4 = cb; c4 < 32; c4 += 4) {
                float4 mx = make_float4(-3.4e38f, -3.4e38f, -3.4e38f, -3.4e38f);
#pragma unroll
                for (int k = 0; k < KNN; k++) {
                    const float4 v = *(const float4*)(Ps + id[k] * NPAD + c4 * 4);
                    mx.x = fmaxf(mx.x, v.x); mx.y = fmaxf(mx.y, v.y);
                    mx.z = fmaxf(mx.z, v.z); mx.w = fmaxf(mx.w, v.w);
                }
                float4 a = *(const float4*)(As + n * NPAD + c4 * 4);
                float4 bcv = *(const float4*)(bc + c4 * 4);
                float4 r;
                r.x = elu1(mx.x + a.x + bcv.x);
                r.y = elu1(mx.y + a.y + bcv.y);
                r.z = elu1(mx.z + a.z + bcv.z);
                r.w = elu1(mx.w + a.w + bcv.w);
                *(float4*)(Xs + n * NPAD + c4 * 4) = r;
            }
        }
    }
    __syncthreads();

    // ---------------- pool + head MLP ----------------
    float* pooled = hd;        // 128
    float* o1 = hd + 128;      // 64
    float* o2 = hd + 192;      // 32
    float* o3 = hd + 224;      // 32
    if (t < 128) {
        float s = 0.f;
#pragma unroll 8
        for (int n = 0; n < NN; n++) s += Xs[n * NPAD + t];
        pooled[t] = s;
    }
    __syncthreads();
    if (t < 64) {
        float s = bo1[t];
        for (int k = 0; k < 128; k++) s = fmaf(pooled[k], Wo1[k * 64 + t], s);
        o1[t] = elu1(s);
    }
    __syncthreads();
    if (t < 32) {
        float s = bo2[t];
        for (int k = 0; k < 64; k++) s = fmaf(o1[k], Wo2[k * 32 + t], s);
        o2[t] = elu1(s);
    }
    __syncthreads();
    if (t < 32) {
        float s = bo3[t];
        for (int k = 0; k < 32; k++) s = fmaf(o2[k], Wo3[k * 32 + t], s);
        o3[t] = elu1(s);
    }
    __syncthreads();
    if (t < 8) {
        float s = bo4[t];
        for (int k = 0; k < 32; k++) s = fmaf(o3[k], Wo4[k * 8 + t], s);
        out[g * 8 + t] = s;
    }
    if (write_batch) {
        for (int l = t; l < NN; l += 256)
            out[NG * 8 + g * NN + l] = (float)g;
    }
}

static const int SMEM_BYTES = (NN * NPAD * 3 + NN * KNN + NN + 256) * 4;  // 108800

extern "C" void kernel_launch(void* const* d_in, const int* in_sizes, int n_in,
                              void* d_out, int out_size) {
    const float* x_pf = (const float*)d_in[0];
    // d_in[1] = batch_pf (implicit: node n belongs to graph n/64)
    const float* W1  = (const float*)d_in[2];
    const float* b1  = (const float*)d_in[3];
    const float* W2  = (const float*)d_in[4];
    const float* b2  = (const float*)d_in[5];
    const float* Wc  = (const float*)d_in[6];
    const float* bc  = (const float*)d_in[7];
    const float* Wo1 = (const float*)d_in[8];
    const float* bo1 = (const float*)d_in[9];
    const float* Wo2 = (const float*)d_in[10];
    const float* bo2 = (const float*)d_in[11];
    const float* Wo3 = (const float*)d_in[12];
    const float* bo3 = (const float*)d_in[13];
    const float* Wo4 = (const float*)d_in[14];
    const float* bo4 = (const float*)d_in[15];

    cudaFuncSetAttribute(net_kernel, cudaFuncAttributeMaxDynamicSharedMemorySize, SMEM_BYTES);

    prep_kernel<<<128, 256>>>(Wc);

    int write_batch = (out_size >= NG * 8 + NG * NN) ? 1 : 0;
    net_kernel<<<NG, 256, SMEM_BYTES>>>(x_pf, W1, b1, W2, b2, bc,
                                        Wo1, bo1, Wo2, bo2, Wo3, bo3, Wo4, bo4,
                                        (float*)d_out, write_batch);
}

// round 2
// speedup vs baseline: 1.0008x; 1.0008x over previous
#include <cuda_runtime.h>

typedef unsigned long long u64;

#define NG   256
#define NN   64
#define KNN  24
#define HID  128
#define NPAD 132   // float stride for 64x128 tiles
#define DPAD 68    // uint stride for 64x64 key matrix

// k-pair-packed weights: each u64 = (w[2kp][c], w[2kp+1][c]) as two fp32 lanes
__device__ u64 g_Wcp[64 * 256];   // edge-conv: cols 0..127 = Wt-Wb ('a'), 128..255 = Wb ('p')
__device__ u64 g_W2p[64 * 128];
__device__ u64 g_W1p[8 * 128];    // K=15 zero-padded to 16

__device__ __forceinline__ void fma2(u64& d, u64 a, u64 b) {
    asm("fma.rn.f32x2 %0, %1, %2, %0;" : "+l"(d) : "l"(a), "l"(b));
}
__device__ __forceinline__ float2 upk(u64 v) {
    float2 f; asm("mov.b64 {%0, %1}, %2;" : "=f"(f.x), "=f"(f.y) : "l"(v)); return f;
}
__device__ __forceinline__ u64 pk(float lo, float hi) {
    u64 r; asm("mov.b64 %0, {%1, %2};" : "=l"(r) : "f"(lo), "f"(hi)); return r;
}
__device__ __forceinline__ float elu1(float x) {
    return x > 0.f ? x : (__expf(x) - 1.f);
}
// monotonic uint encoding of float (total order matching < on floats)
__device__ __forceinline__ unsigned fkey(float d) {
    unsigned u = __float_as_uint(d);
    return ((int)u < 0) ? ~u : (u | 0x80000000u);
}

__global__ void prep_kernel(const float* __restrict__ Wc,
                            const float* __restrict__ W1,
                            const float* __restrict__ W2) {
    int i = blockIdx.x * blockDim.x + threadIdx.x;
    if (i < 64 * 256) {
        int kp = i >> 8, c = i & 255;
        float lo, hi;
        if (c < HID) {
            lo = Wc[(2 * kp) * HID + c]     - Wc[(HID + 2 * kp) * HID + c];
            hi = Wc[(2 * kp + 1) * HID + c] - Wc[(HID + 2 * kp + 1) * HID + c];
        } else {
            lo = Wc[(HID + 2 * kp) * HID + (c - HID)];
            hi = Wc[(HID + 2 * kp + 1) * HID + (c - HID)];
        }
        g_Wcp[i] = pk(lo, hi);
    }
    int j = i - 64 * 256;
    if (j >= 0 && j < 64 * 128) {
        int kp = j >> 7, c = j & 127;
        g_W2p[j] = pk(W2[(2 * kp) * HID + c], W2[(2 * kp + 1) * HID + c]);
    }
    int l = i - 64 * 256 - 64 * 128;
    if (l >= 0 && l < 8 * 128) {
        int kp = l >> 7, c = l & 127;
        float lo = W1[(2 * kp) * HID + c];
        float hi = (2 * kp + 1 < 15) ? W1[(2 * kp + 1) * HID + c] : 0.f;
        g_W1p[l] = pk(lo, hi);
    }
}

// Out[64x128] = elu( Xin[64 x 2*KP] @ W + bias ), Out stride NPAD. W k-pair packed, row stride 128.
__device__ __forceinline__ void gemm_act(const float* __restrict__ Xin, int xs, int KP,
                                         const u64* __restrict__ Wp,
                                         const float* __restrict__ bias,
                                         float* __restrict__ Out, int t) {
    int n0 = (t >> 5) * 8;
    int c0 = (t & 31) * 4;
    u64 acc[8][4];
#pragma unroll
    for (int i = 0; i < 8; i++) { acc[i][0] = 0; acc[i][1] = 0; acc[i][2] = 0; acc[i][3] = 0; }
#pragma unroll 4
    for (int kp = 0; kp < KP; kp++) {
        const u64* wr = Wp + kp * 128 + c0;
        ulonglong2 wa = *(const ulonglong2*)(wr);
        ulonglong2 wb = *(const ulonglong2*)(wr + 2);
        u64 xv[8];
#pragma unroll
        for (int i = 0; i < 8; i++) xv[i] = *(const u64*)(Xin + (n0 + i) * xs + 2 * kp);
#pragma unroll
        for (int i = 0; i < 8; i++) {
            fma2(acc[i][0], xv[i], wa.x);
            fma2(acc[i][1], xv[i], wa.y);
            fma2(acc[i][2], xv[i], wb.x);
            fma2(acc[i][3], xv[i], wb.y);
        }
    }
    float4 b = *(const float4*)(bias + c0);
#pragma unroll
    for (int i = 0; i < 8; i++) {
        float2 e0 = upk(acc[i][0]), e1 = upk(acc[i][1]), e2 = upk(acc[i][2]), e3 = upk(acc[i][3]);
        float4 r;
        r.x = elu1(e0.x + e0.y + b.x);
        r.y = elu1(e1.x + e1.y + b.y);
        r.z = elu1(e2.x + e2.y + b.z);
        r.w = elu1(e3.x + e3.y + b.w);
        *(float4*)(Out + (n0 + i) * NPAD + c0) = r;
    }
}

// Out[64x128] = Xin[64x128] @ W (no bias/act). W k-pair packed, row stride 256 (edge weight).
__device__ __forceinline__ void gemm_raw(const float* __restrict__ Xin,
                                         const u64* __restrict__ Wp,
                                         float* __restrict__ Out, int t) {
    int n0 = (t >> 5) * 8;
    int c0 = (t & 31) * 4;
    u64 acc[8][4];
#pragma unroll
    for (int i = 0; i < 8; i++) { acc[i][0] = 0; acc[i][1] = 0; acc[i][2] = 0; acc[i][3] = 0; }
#pragma unroll 4
    for (int kp = 0; kp < 64; kp++) {
        const u64* wr = Wp + kp * 256 + c0;
        ulonglong2 wa = *(const ulonglong2*)(wr);
        ulonglong2 wb = *(const ulonglong2*)(wr + 2);
        u64 xv[8];
#pragma unroll
        for (int i = 0; i < 8; i++) xv[i] = *(const u64*)(Xin + (n0 + i) * NPAD + 2 * kp);
#pragma unroll
        for (int i = 0; i < 8; i++) {
            fma2(acc[i][0], xv[i], wa.x);
            fma2(acc[i][1], xv[i], wa.y);
            fma2(acc[i][2], xv[i], wb.x);
            fma2(acc[i][3], xv[i], wb.y);
        }
    }
#pragma unroll
    for (int i = 0; i < 8; i++) {
        float2 e0 = upk(acc[i][0]), e1 = upk(acc[i][1]), e2 = upk(acc[i][2]), e3 = upk(acc[i][3]);
        float4 r;
        r.x = e0.x + e0.y;
        r.y = e1.x + e1.y;
        r.z = e2.x + e2.y;
        r.w = e3.x + e3.y;
        *(float4*)(Out + (n0 + i) * NPAD + c0) = r;
    }
}

__global__ __launch_bounds__(256, 2)
void net_kernel(const float* __restrict__ x_pf,
                const float* __restrict__ b1, const float* __restrict__ b2,
                const float* __restrict__ bc,
                const float* __restrict__ Wo1, const float* __restrict__ bo1,
                const float* __restrict__ Wo2, const float* __restrict__ bo2,
                const float* __restrict__ Wo3, const float* __restrict__ bo3,
                const float* __restrict__ Wo4, const float* __restrict__ bo4,
                float* __restrict__ out, int write_batch) {
    extern __shared__ float sm[];
    float* Xs = sm;                   // 64*132 current node features
    float* As = Xs + NN * NPAD;       // 64*132 'a' term (aliases key matrix + Xi scratch)
    float* Ps = As + NN * NPAD;       // 64*132 'p' term (also h1 scratch in stage 1)
    int*   idxs = (int*)(Ps + NN * NPAD);          // 64*24 KNN indices
    float* sq = (float*)(idxs + NN * KNN);         // 64 squared norms
    float* hd = sq + NN;                           // 256 floats head scratch
    unsigned* dsu = (unsigned*)As;                 // 64 x DPAD 32-bit keys

    int g = blockIdx.x;
    int t = threadIdx.x;

    // ---------------- Stage 1: h = elu(elu(x@W1+b1)@W2+b2) ----------------
    float* Xi = As;  // temp [64][16], col 15 zeroed (k padding for packed W1)
    for (int i = t; i < NN * 16; i += 256) {
        int n = i >> 4, f = i & 15;
        Xi[i] = (f < 15) ? x_pf[(g * NN + n) * 15 + f] : 0.f;
    }
    __syncthreads();
    gemm_act(Xi, 16, 8, g_W1p, b1, Ps, t);
    __syncthreads();
    gemm_act(Ps, NPAD, 64, g_W2p, b2, Xs, t);

    // ---------------- 3 x EdgeConv ----------------
    for (int layer = 0; layer < 3; layer++) {
        __syncthreads();  // Xs ready
        // squared norms (packed over k)
        if (t < NN) {
            u64 a0 = 0, a1 = 0;
#pragma unroll 8
            for (int k4 = 0; k4 < 32; k4++) {
                ulonglong2 v = *(const ulonglong2*)(Xs + t * NPAD + k4 * 4);
                fma2(a0, v.x, v.x);
                fma2(a1, v.y, v.y);
            }
            float2 e0 = upk(a0), e1 = upk(a1);
            sq[t] = (e0.x + e0.y) + (e1.x + e1.y);
        }
        __syncthreads();
        // pairwise distance keys (k-packed 4x4 tile per thread)
        {
            int r0 = (t >> 4) * 4, c0d = (t & 15) * 4;
            u64 acc2[4][4];
#pragma unroll
            for (int i = 0; i < 4; i++)
#pragma unroll
                for (int j = 0; j < 4; j++) acc2[i][j] = 0;
#pragma unroll 2
            for (int k4 = 0; k4 < 32; k4++) {
                ulonglong2 av[4], bv[4];
#pragma unroll
                for (int i = 0; i < 4; i++) av[i] = *(const ulonglong2*)(Xs + (r0 + i) * NPAD + k4 * 4);
#pragma unroll
                for (int j = 0; j < 4; j++) bv[j] = *(const ulonglong2*)(Xs + (c0d + j) * NPAD + k4 * 4);
#pragma unroll
                for (int i = 0; i < 4; i++)
#pragma unroll
                    for (int j = 0; j < 4; j++) {
                        fma2(acc2[i][j], av[i].x, bv[j].x);
                        fma2(acc2[i][j], av[i].y, bv[j].y);
                    }
            }
#pragma unroll
            for (int i = 0; i < 4; i++)
#pragma unroll
                for (int j = 0; j < 4; j++) {
                    float2 e = upk(acc2[i][j]);
                    float d = sq[r0 + i] + sq[c0d + j] - 2.f * (e.x + e.y);
                    dsu[(r0 + i) * DPAD + (c0d + j)] = fkey(d);
                }
        }
        __syncthreads();
        // exact top-K by rank counting (keys assumed distinct; rank is the slot)
        {
            int i = t >> 2, jb = (t & 3) * 16;
            unsigned kj[16];
#pragma unroll
            for (int jj = 0; jj < 16; jj++) kj[jj] = dsu[i * DPAD + jb + jj];
            int rk[16];
#pragma unroll
            for (int jj = 0; jj < 16; jj++) rk[jj] = 0;
            for (int m = 0; m < 64; m++) {
                unsigned km = dsu[i * DPAD + m];
#pragma unroll
                for (int jj = 0; jj < 16; jj++) rk[jj] += (km < kj[jj]) ? 1 : 0;
            }
#pragma unroll
            for (int jj = 0; jj < 16; jj++)
                if (rk[jj] < KNN) idxs[i * KNN + rk[jj]] = jb + jj;
        }
        __syncthreads();  // keys dead; GEMM may overwrite As
        gemm_raw(Xs, g_Wcp, As, t);         // 'a' = X @ (Wt - Wb)
        gemm_raw(Xs, g_Wcp + 128, Ps, t);   // 'p' = X @ Wb
        __syncthreads();
        // gather-max over neighbors, then single elu (elu is monotonic)
        {
            int n = t >> 2, cb = t & 3;
            int id[KNN];
#pragma unroll
            for (int k = 0; k < KNN; k++) id[k] = idxs[n * KNN + k];
            for (int c4 = cb; c4 < 32; c4 += 4) {
                float4 mx = make_float4(-3.4e38f, -3.4e38f, -3.4e38f, -3.4e38f);
#pragma unroll
                for (int k = 0; k < KNN; k++) {
                    const float4 v = *(const float4*)(Ps + id[k] * NPAD + c4 * 4);
                    mx.x = fmaxf(mx.x, v.x); mx.y = fmaxf(mx.y, v.y);
                    mx.z = fmaxf(mx.z, v.z); mx.w = fmaxf(mx.w, v.w);
                }
                float4 a = *(const float4*)(As + n * NPAD + c4 * 4);
                float4 bcv = *(const float4*)(bc + c4 * 4);
                float4 r;
                r.x = elu1(mx.x + a.x + bcv.x);
                r.y = elu1(mx.y + a.y + bcv.y);
                r.z = elu1(mx.z + a.z + bcv.z);
                r.w = elu1(mx.w + a.w + bcv.w);
                *(float4*)(Xs + n * NPAD + c4 * 4) = r;
            }
        }
    }
    __syncthreads();

    // ---------------- pool + head MLP ----------------
    float* pooled = hd;        // 128
    float* o1 = hd + 128;      // 64
    float* o2 = hd + 192;      // 32
    float* o3 = hd + 224;      // 32
    if (t < 128) {
        float s = 0.f;
#pragma unroll 8
        for (int n = 0; n < NN; n++) s += Xs[n * NPAD + t];
        pooled[t] = s;
    }
    __syncthreads();
    if (t < 64) {
        float s = bo1[t];
        for (int k = 0; k < 128; k++) s = fmaf(pooled[k], Wo1[k * 64 + t], s);
        o1[t] = elu1(s);
    }
    __syncthreads();
    if (t < 32) {
        float s = bo2[t];
        for (int k = 0; k < 64; k++) s = fmaf(o1[k], Wo2[k * 32 + t], s);
        o2[t] = elu1(s);
    }
    __syncthreads();
    if (t < 32) {
        float s = bo3[t];
        for (int k = 0; k < 32; k++) s = fmaf(o2[k], Wo3[k * 32 + t], s);
        o3[t] = elu1(s);
    }
    __syncthreads();
    if (t < 8) {
        float s = bo4[t];
        for (int k = 0; k < 32; k++) s = fmaf(o3[k], Wo4[k * 8 + t], s);
        out[g * 8 + t] = s;
    }
    if (write_batch) {
        for (int l = t; l < NN; l += 256)
            out[NG * 8 + g * NN + l] = (float)g;
    }
}

static const int SMEM_BYTES = (NN * NPAD * 3 + NN * KNN + NN + 256) * 4;  // 108800

extern "C" void kernel_launch(void* const* d_in, const int* in_sizes, int n_in,
                              void* d_out, int out_size) {
    const float* x_pf = (const float*)d_in[0];
    // d_in[1] = batch_pf (implicit: node n belongs to graph n/64)
    const float* W1  = (const float*)d_in[2];
    const float* b1  = (const float*)d_in[3];
    const float* W2  = (const float*)d_in[4];
    const float* b2  = (const float*)d_in[5];
    const float* Wc  = (const float*)d_in[6];
    const float* bc  = (const float*)d_in[7];
    const float* Wo1 = (const float*)d_in[8];
    const float* bo1 = (const float*)d_in[9];
    const float* Wo2 = (const float*)d_in[10];
    const float* bo2 = (const float*)d_in[11];
    const float* Wo3 = (const float*)d_in[12];
    const float* bo3 = (const float*)d_in[13];
    const float* Wo4 = (const float*)d_in[14];
    const float* bo4 = (const float*)d_in[15];

    cudaFuncSetAttribute(net_kernel, cudaFuncAttributeMaxDynamicSharedMemorySize, SMEM_BYTES);

    prep_kernel<<<100, 256>>>(Wc, W1, W2);

    int write_batch = (out_size >= NG * 8 + NG * NN) ? 1 : 0;
    net_kernel<<<NG, 256, SMEM_BYTES>>>(x_pf, b1, b2, bc,
                                        Wo1, bo1, Wo2, bo2, Wo3, bo3, Wo4, bo4,
                                        (float*)d_out, write_batch);
}

// round 4
// speedup vs baseline: 1.0265x; 1.0256x over previous
#include <cuda_runtime.h>

typedef unsigned long long u64;

#define NG   256
#define NN   64
#define KNN  24
#define HID  128
#define NPAD 132   // float stride for 64x128 tiles
#define DPAD 68    // uint stride for 64x64 key matrix
#define NT   512   // threads per CTA

// k-pair-packed weights: each u64 = (w[2kp][c], w[2kp+1][c]) as two fp32 lanes
__device__ u64 g_Wcp[64 * 256];   // edge-conv: cols 0..127 = Wt-Wb ('a'), 128..255 = Wb ('p')
__device__ u64 g_W2p[64 * 128];
__device__ u64 g_W1p[8 * 128];    // K=15 zero-padded to 16

__device__ __forceinline__ void fma2(u64& d, u64 a, u64 b) {
    asm("fma.rn.f32x2 %0, %1, %2, %0;" : "+l"(d) : "l"(a), "l"(b));
}
__device__ __forceinline__ float2 upk(u64 v) {
    float2 f; asm("mov.b64 {%0, %1}, %2;" : "=f"(f.x), "=f"(f.y) : "l"(v)); return f;
}
__device__ __forceinline__ u64 pk(float lo, float hi) {
    u64 r; asm("mov.b64 %0, {%1, %2};" : "=l"(r) : "f"(lo), "f"(hi)); return r;
}
__device__ __forceinline__ float elu1(float x) {
    return x > 0.f ? x : (__expf(x) - 1.f);
}
// monotonic uint encoding of float (total order matching < on floats)
__device__ __forceinline__ unsigned fkey(float d) {
    unsigned u = __float_as_uint(d);
    return ((int)u < 0) ? ~u : (u | 0x80000000u);
}

__global__ void prep_kernel(const float* __restrict__ Wc,
                            const float* __restrict__ W1,
                            const float* __restrict__ W2) {
    int i = blockIdx.x * blockDim.x + threadIdx.x;
    if (i < 64 * 256) {
        int kp = i >> 8, c = i & 255;
        float lo, hi;
        if (c < HID) {
            lo = Wc[(2 * kp) * HID + c]     - Wc[(HID + 2 * kp) * HID + c];
            hi = Wc[(2 * kp + 1) * HID + c] - Wc[(HID + 2 * kp + 1) * HID + c];
        } else {
            lo = Wc[(HID + 2 * kp) * HID + (c - HID)];
            hi = Wc[(HID + 2 * kp + 1) * HID + (c - HID)];
        }
        g_Wcp[i] = pk(lo, hi);
    }
    int j = i - 64 * 256;
    if (j >= 0 && j < 64 * 128) {
        int kp = j >> 7, c = j & 127;
        g_W2p[j] = pk(W2[(2 * kp) * HID + c], W2[(2 * kp + 1) * HID + c]);
    }
    int l = i - 64 * 256 - 64 * 128;
    if (l >= 0 && l < 8 * 128) {
        int kp = l >> 7, c = l & 127;
        float lo = W1[(2 * kp) * HID + c];
        float hi = (2 * kp + 1 < 15) ? W1[(2 * kp + 1) * HID + c] : 0.f;
        g_W1p[l] = pk(lo, hi);
    }
}

// Out[64x128] = act?( Xin[64 x 2*KP] @ W + bias ), Out stride NPAD.
// W k-pair packed, row stride ws (u64s). 512 threads: 4 rows/warp, 4 cols/thread.
template<int DO_ACT>
__device__ __forceinline__ void gemm512(const float* __restrict__ Xin, int xs, int KP,
                                        const u64* __restrict__ Wp, int ws,
                                        const float* __restrict__ bias,
                                        float* __restrict__ Out, int t) {
    int n0 = (t >> 5) * 4;     // 16 warps x 4 rows
    int c0 = (t & 31) * 4;     // 32 lanes x 4 cols
    u64 acc[4][4];
#pragma unroll
    for (int i = 0; i < 4; i++) { acc[i][0] = 0; acc[i][1] = 0; acc[i][2] = 0; acc[i][3] = 0; }
#pragma unroll 4
    for (int kp = 0; kp < KP; kp++) {
        const u64* wr = Wp + kp * ws + c0;
        ulonglong2 wa = *(const ulonglong2*)(wr);
        ulonglong2 wb = *(const ulonglong2*)(wr + 2);
        u64 xv[4];
#pragma unroll
        for (int i = 0; i < 4; i++) xv[i] = *(const u64*)(Xin + (n0 + i) * xs + 2 * kp);
#pragma unroll
        for (int i = 0; i < 4; i++) {
            fma2(acc[i][0], xv[i], wa.x);
            fma2(acc[i][1], xv[i], wa.y);
            fma2(acc[i][2], xv[i], wb.x);
            fma2(acc[i][3], xv[i], wb.y);
        }
    }
    float4 b;
    if (DO_ACT) b = *(const float4*)(bias + c0);
#pragma unroll
    for (int i = 0; i < 4; i++) {
        float2 e0 = upk(acc[i][0]), e1 = upk(acc[i][1]), e2 = upk(acc[i][2]), e3 = upk(acc[i][3]);
        float4 r;
        if (DO_ACT) {
            r.x = elu1(e0.x + e0.y + b.x);
            r.y = elu1(e1.x + e1.y + b.y);
            r.z = elu1(e2.x + e2.y + b.z);
            r.w = elu1(e3.x + e3.y + b.w);
        } else {
            r.x = e0.x + e0.y; r.y = e1.x + e1.y; r.z = e2.x + e2.y; r.w = e3.x + e3.y;
        }
        *(float4*)(Out + (n0 + i) * NPAD + c0) = r;
    }
}

__global__ __launch_bounds__(NT, 2)
void net_kernel(const float* __restrict__ x_pf,
                const float* __restrict__ b1, const float* __restrict__ b2,
                const float* __restrict__ bc,
                const float* __restrict__ Wo1, const float* __restrict__ bo1,
                const float* __restrict__ Wo2, const float* __restrict__ bo2,
                const float* __restrict__ Wo3, const float* __restrict__ bo3,
                const float* __restrict__ Wo4, const float* __restrict__ bo4,
                float* __restrict__ out, int write_batch) {
    extern __shared__ float sm[];
    float* Xs = sm;                   // 64*132 current node features
    float* As = Xs + NN * NPAD;       // 64*132 'a' term (aliases key matrix + Xi scratch)
    float* Ps = As + NN * NPAD;       // 64*132 'p' term (also h1 scratch in stage 1)
    int*   idxs = (int*)(Ps + NN * NPAD);          // 64*24 KNN indices
    float* sq = (float*)(idxs + NN * KNN);         // 64 squared norms
    float* hd = sq + NN;                           // 256 floats head scratch
    unsigned* dsu = (unsigned*)As;                 // 64 x DPAD 32-bit keys

    int g = blockIdx.x;
    int t = threadIdx.x;

    // ---------------- Stage 1: h = elu(elu(x@W1+b1)@W2+b2) ----------------
    float* Xi = As;  // temp [64][16], col 15 zeroed (k padding for packed W1)
    for (int i = t; i < NN * 16; i += NT) {
        int n = i >> 4, f = i & 15;
        Xi[i] = (f < 15) ? x_pf[(g * NN + n) * 15 + f] : 0.f;
    }
    __syncthreads();
    gemm512<1>(Xi, 16, 8, g_W1p, 128, b1, Ps, t);
    __syncthreads();
    gemm512<1>(Ps, NPAD, 64, g_W2p, 128, b2, Xs, t);

    // ---------------- 3 x EdgeConv ----------------
    for (int layer = 0; layer < 3; layer++) {
        __syncthreads();  // Xs ready
        // squared norms (packed over k)
        if (t < NN) {
            u64 a0 = 0, a1 = 0;
#pragma unroll 8
            for (int k4 = 0; k4 < 32; k4++) {
                ulonglong2 v = *(const ulonglong2*)(Xs + t * NPAD + k4 * 4);
                fma2(a0, v.x, v.x);
                fma2(a1, v.y, v.y);
            }
            float2 e0 = upk(a0), e1 = upk(a1);
            sq[t] = (e0.x + e0.y) + (e1.x + e1.y);
        }
        __syncthreads();
        // pairwise distance keys: 2 rows x 4 strided cols per thread
        // col rows {c, c+16, c+32, c+48} with c = t&15 -> 2-way (not 8-way) LDS conflicts
        {
            int r0 = (t >> 4) * 2;       // 32 groups x 2 rows
            int cbase = t & 15;          // cols cbase + 16*jj
            u64 acc2[2][4];
#pragma unroll
            for (int i = 0; i < 2; i++)
#pragma unroll
                for (int j = 0; j < 4; j++) acc2[i][j] = 0;
#pragma unroll 2
            for (int k4 = 0; k4 < 32; k4++) {
                ulonglong2 av[2], bv[4];
#pragma unroll
                for (int i = 0; i < 2; i++) av[i] = *(const ulonglong2*)(Xs + (r0 + i) * NPAD + k4 * 4);
#pragma unroll
                for (int j = 0; j < 4; j++) bv[j] = *(const ulonglong2*)(Xs + (cbase + 16 * j) * NPAD + k4 * 4);
#pragma unroll
                for (int i = 0; i < 2; i++)
#pragma unroll
                    for (int j = 0; j < 4; j++) {
                        fma2(acc2[i][j], av[i].x, bv[j].x);
                        fma2(acc2[i][j], av[i].y, bv[j].y);
                    }
            }
#pragma unroll
            for (int i = 0; i < 2; i++)
#pragma unroll
                for (int j = 0; j < 4; j++) {
                    float2 e = upk(acc2[i][j]);
                    int cc = cbase + 16 * j;
                    float d = sq[r0 + i] + sq[cc] - 2.f * (e.x + e.y);
                    dsu[(r0 + i) * DPAD + cc] = fkey(d);
                }
        }
        __syncthreads();
        // exact top-K by rank counting (keys assumed distinct; rank is the slot)
        {
            int i = t >> 3, jb = (t & 7) * 8;
            unsigned kj[8];
#pragma unroll
            for (int jj = 0; jj < 8; jj++) kj[jj] = dsu[i * DPAD + jb + jj];
            int rk[8];
#pragma unroll
            for (int jj = 0; jj < 8; jj++) rk[jj] = 0;
#pragma unroll 4
            for (int m = 0; m < 64; m++) {
                unsigned km = dsu[i * DPAD + m];
#pragma unroll
                for (int jj = 0; jj < 8; jj++) rk[jj] += (km < kj[jj]) ? 1 : 0;
            }
#pragma unroll
            for (int jj = 0; jj < 8; jj++)
                if (rk[jj] < KNN) idxs[i * KNN + rk[jj]] = jb + jj;
        }
        __syncthreads();  // keys dead; GEMM may overwrite As
        gemm512<0>(Xs, NPAD, 64, g_Wcp, 256, (const float*)0, As, t);         // 'a' = X @ (Wt - Wb)
        gemm512<0>(Xs, NPAD, 64, g_Wcp + 128, 256, (const float*)0, Ps, t);   // 'p' = X @ Wb
        __syncthreads();
        // gather-max over neighbors, then single elu (elu is monotonic)
        {
            int n = t >> 3, cb = t & 7;
            int id[KNN];
#pragma unroll
            for (int k = 0; k < KNN; k++) id[k] = idxs[n * KNN + k];
#pragma unroll
            for (int c4 = cb; c4 < 32; c4 += 8) {
                float4 mx = make_float4(-3.4e38f, -3.4e38f, -3.4e38f, -3.4e38f);
#pragma unroll
                for (int k = 0; k < KNN; k++) {
                    const float4 v = *(const float4*)(Ps + id[k] * NPAD + c4 * 4);
                    mx.x = fmaxf(mx.x, v.x); mx.y = fmaxf(mx.y, v.y);
                    mx.z = fmaxf(mx.z, v.z); mx.w = fmaxf(mx.w, v.w);
                }
                float4 a = *(const float4*)(As + n * NPAD + c4 * 4);
                float4 bcv = *(const float4*)(bc + c4 * 4);
                float4 r;
                r.x = elu1(mx.x + a.x + bcv.x);
                r.y = elu1(mx.y + a.y + bcv.y);
                r.z = elu1(mx.z + a.z + bcv.z);
                r.w = elu1(mx.w + a.w + bcv.w);
                *(float4*)(Xs + n * NPAD + c4 * 4) = r;
            }
        }
    }
    __syncthreads();

    // ---------------- pool + head MLP ----------------
    float* pooled = hd;        // 128
    float* o1 = hd + 128;      // 64
    float* o2 = hd + 192;      // 32
    float* o3 = hd + 224;      // 32
    if (t < 128) {
        float s = 0.f;
#pragma unroll 8
        for (int n = 0; n < NN; n++) s += Xs[n * NPAD + t];
        pooled[t] = s;
    }
    __syncthreads();
    if (t < 64) {
        float s = bo1[t];
        for (int k = 0; k < 128; k++) s = fmaf(pooled[k], Wo1[k * 64 + t], s);
        o1[t] = elu1(s);
    }
    __syncthreads();
    if (t < 32) {
        float s = bo2[t];
        for (int k = 0; k < 64; k++) s = fmaf(o1[k], Wo2[k * 32 + t], s);
        o2[t] = elu1(s);
    }
    __syncthreads();
    if (t < 32) {
        float s = bo3[t];
        for (int k = 0; k < 32; k++) s = fmaf(o2[k], Wo3[k * 32 + t], s);
        o3[t] = elu1(s);
    }
    __syncthreads();
    if (t < 8) {
        float s = bo4[t];
        for (int k = 0; k < 32; k++) s = fmaf(o3[k], Wo4[k * 8 + t], s);
        out[g * 8 + t] = s;
    }
    if (write_batch) {
        for (int l = t; l < NN; l += NT)
            out[NG * 8 + g * NN + l] = (float)g;
    }
}

static const int SMEM_BYTES = (NN * NPAD * 3 + NN * KNN + NN + 256) * 4;  // 108800

extern "C" void kernel_launch(void* const* d_in, const int* in_sizes, int n_in,
                              void* d_out, int out_size) {
    const float* x_pf = (const float*)d_in[0];
    // d_in[1] = batch_pf (implicit: node n belongs to graph n/64)
    const float* W1  = (const float*)d_in[2];
    const float* b1  = (const float*)d_in[3];
    const float* W2  = (const float*)d_in[4];
    const float* b2  = (const float*)d_in[5];
    const float* Wc  = (const float*)d_in[6];
    const float* bc  = (const float*)d_in[7];
    const float* Wo1 = (const float*)d_in[8];
    const float* bo1 = (const float*)d_in[9];
    const float* Wo2 = (const float*)d_in[10];
    const float* bo2 = (const float*)d_in[11];
    const float* Wo3 = (const float*)d_in[12];
    const float* bo3 = (const float*)d_in[13];
    const float* Wo4 = (const float*)d_in[14];
    const float* bo4 = (const float*)d_in[15];

    cudaFuncSetAttribute(net_kernel, cudaFuncAttributeMaxDynamicSharedMemorySize, SMEM_BYTES);

    prep_kernel<<<100, 256>>>(Wc, W1, W2);

    int write_batch = (out_size >= NG * 8 + NG * NN) ? 1 : 0;
    net_kernel<<<NG, NT, SMEM_BYTES>>>(x_pf, b1, b2, bc,
                                       Wo1, bo1, Wo2, bo2, Wo3, bo3, Wo4, bo4,
                                       (float*)d_out, write_batch);
}